// round 16
// baseline (speedup 1.0000x reference)
#include <cuda_runtime.h>
#include <cuda_fp16.h>
#include <cstdint>

// ---------------- problem constants ----------------
constexpr int B_   = 2;
constexpr int C_   = 256;
constexpr int Hh   = 48;
constexpr int Ww   = 48;
constexpr int H3   = 144;
constexpr int HO   = 142, WO = 142;
constexpr int NPB  = HO * WO;        // 20164
constexpr int NA   = 5;

// Winograd F(2,3) along v: 4 components, K = C*3
constexpr int KW   = C_ * 3;         // 768
constexpr int VW   = 72;             // V row width (71 valid tiles + 1 pad)
constexpr int PLV  = H3 * VW;        // 10368
constexpr size_t CPSTR = (size_t)NA * B_ * C_ * PLV;
constexpr int PADE = 8192;

// GEMM tiling: 128co x 128n, 256 threads, CHUNK 64, 2 stages
constexpr int NPAD  = 10240;         // 80 tiles * 128
constexpr int NT    = 80;
constexpr int CHUNK = 64;
constexpr int NCH   = KW / CHUNK;    // 12
constexpr int AROWB = 144;           // 128B payload + 16 pad
constexpr int BROWB = 272;           // 256B payload + 16 pad
constexpr int OFF_B = 128 * AROWB;                 // 18432
constexpr int STAGE = OFF_B + 64 * BROWB;          // 35840
constexpr int SMEM_TOTAL = 2 * STAGE;              // 71680

constexpr int ATT_SMEM = (8192 + 32768 + 512 + 64 + 2048) * 4;  // 174336

// vector-iteration space over M planes: 142 rows x 9 octs (8 tiles each)
constexpr int NITER8 = HO * 9;       // 1278

// ---------------- static scratch ----------------
__device__ __align__(16) unsigned short g_v[4 * CPSTR + PADE];
__device__ __align__(16) unsigned short g_wU[4 * C_ * KW];
__device__ __align__(16) __half g_M[(size_t)4 * NA * B_ * C_ * NPAD];
__device__ float g_fsum[B_ * C_];
__device__ float g_att[B_ * 4 * C_];

// ---------------- angle offset tables ----------------
#define S2  1.4142135623730951
#define S2H 0.7071067811865476
__constant__ float c_ox[45] = {
    0.f,0.f,0.f,0.f,0.f,0.f,0.f,0.f,0.f,
    (float)(1.0-S2), (float)(1.0-S2H), 1.f, (float)(-S2H), 0.f, (float)(S2H),
    -1.f, (float)(S2H-1.0), (float)(S2-1.0),
    0.f,1.f,2.f,-1.f,0.f,1.f,-2.f,-1.f,0.f,
    1.f, (float)(1.0+S2H), (float)(1.0+S2), (float)(-S2H), 0.f, (float)(S2H),
    (float)(-1.0-S2), (float)(-1.0-S2H), -1.f,
    2.f,2.f,2.f,0.f,0.f,0.f,-2.f,-2.f,-2.f
};
__constant__ float c_oy[45] = {
    0.f,0.f,0.f,0.f,0.f,0.f,0.f,0.f,0.f,
    1.f, (float)(S2H), (float)(S2-1.0), (float)(1.0-S2H), 0.f, (float)(S2H-1.0),
    (float)(1.0-S2), (float)(-S2H), -1.f,
    2.f,1.f,0.f,1.f,0.f,-1.f,0.f,-1.f,-2.f,
    (float)(1.0+S2), (float)(S2H), -1.f, (float)(1.0+S2H), 0.f, (float)(-1.0-S2H),
    1.f, (float)(-S2H), (float)(1.0+S2),
    2.f,0.f,-2.f,2.f,0.f,-2.f,2.f,0.f,-2.f
};
__constant__ int c_oxi[27] = {
    0,0,0,0,0,0,0,0,0,
    0,1,2,-1,0,1,-2,-1,0,
    2,2,2,0,0,0,-2,-2,-2
};
__constant__ int c_oyi[27] = {
    0,0,0,0,0,0,0,0,0,
    2,1,0,1,0,-1,0,-1,-2,
    2,0,-2,2,0,-2,2,0,-2
};

// ---------------- helpers ----------------
__device__ __forceinline__ uint32_t smem_u32(const void* p) {
    uint32_t a;
    asm("{ .reg .u64 t; cvta.to.shared.u64 t, %1; cvt.u32.u64 %0, t; }" : "=r"(a) : "l"(p));
    return a;
}
__device__ __forceinline__ void cpasync16(uint32_t dst, const void* src) {
    asm volatile("cp.async.cg.shared.global [%0], [%1], 16;" :: "r"(dst), "l"(src));
}
__device__ __forceinline__ void cp_commit() {
    asm volatile("cp.async.commit_group;" ::: "memory");
}
__device__ __forceinline__ void cp_wait0() {
    asm volatile("cp.async.wait_group 0;" ::: "memory");
}
__device__ __forceinline__ void ldmx4(uint32_t* r, uint32_t addr) {
    asm volatile("ldmatrix.sync.aligned.m8n8.x4.shared.b16 {%0,%1,%2,%3}, [%4];"
                 : "=r"(r[0]), "=r"(r[1]), "=r"(r[2]), "=r"(r[3]) : "r"(addr));
}
__device__ __forceinline__ void ldmx4t(uint32_t* r, uint32_t addr) {
    asm volatile("ldmatrix.sync.aligned.m8n8.x4.trans.shared.b16 {%0,%1,%2,%3}, [%4];"
                 : "=r"(r[0]), "=r"(r[1]), "=r"(r[2]), "=r"(r[3]) : "r"(addr));
}
__device__ __forceinline__ void mma_fp16(float4& d, const uint32_t a[4], uint32_t b0, uint32_t b1) {
    asm volatile("mma.sync.aligned.m16n8k16.row.col.f32.f16.f16.f32 "
                 "{%0,%1,%2,%3}, {%4,%5,%6,%7}, {%8,%9}, {%0,%1,%2,%3};"
                 : "+f"(d.x), "+f"(d.y), "+f"(d.z), "+f"(d.w)
                 : "r"(a[0]), "r"(a[1]), "r"(a[2]), "r"(a[3]), "r"(b0), "r"(b1));
}
__device__ __forceinline__ void up8(uint4 v, float* f) {
    float2 a = __half22float2(*(__half2*)&v.x);
    float2 b = __half22float2(*(__half2*)&v.y);
    float2 c = __half22float2(*(__half2*)&v.z);
    float2 d = __half22float2(*(__half2*)&v.w);
    f[0] = a.x; f[1] = a.y; f[2] = b.x; f[3] = b.y;
    f[4] = c.x; f[5] = c.y; f[6] = d.x; f[7] = d.y;
}

// ---------------- 0) prep: weight winograd transform ----------------
__global__ void prep_kernel(const float* __restrict__ w) {
    int i = blockIdx.x * blockDim.x + threadIdx.x;
    if (i >= C_ * KW) return;
    int co = i / KW;
    int k  = i - co * KW;          // ci*3 + ki
    int ci = k / 3, ki = k - ci * 3;
    const float* gp = w + (((size_t)co * C_ + ci) * 3 + ki) * 3;
    float g0 = gp[0], g1 = gp[1], g2 = gp[2];
    g_wU[(0 * C_ + co) * KW + k] = __half_as_ushort(__float2half_rn(g0));
    g_wU[(1 * C_ + co) * KW + k] = __half_as_ushort(__float2half_rn(0.5f * (g0 + g1 + g2)));
    g_wU[(2 * C_ + co) * KW + k] = __half_as_ushort(__float2half_rn(0.5f * (g0 - g1 + g2)));
    g_wU[(3 * C_ + co) * KW + k] = __half_as_ushort(__float2half_rn(g2));
}

// ---------------- 1) fused bilinear resample + V transform ----------------
// grid: (81, 64, NA*B_), block 256 = 4 channels x 64 ip-slots
__global__ void sampleV_kernel(const float* __restrict__ x) {
    int ip = blockIdx.x * 64 + (threadIdx.x & 63);  // [0, 5184)
    int c  = blockIdx.y * 4 + (threadIdx.x >> 6);
    int ab = blockIdx.z;
    int a  = ab >> 1, bb = ab & 1;

    int r  = ip / 36;
    int tp = ip - r * 36;

    int i = r / 3, ki = r - i * 3;
    const float* xp = x + (bb * C_ + c) * (Hh * Ww);

    float s[6];
    int jmax = (tp == 35) ? 4 : 6;
    for (int j = 0; j < 6; j++) {
        if (j >= jmax) { s[j] = 0.f; continue; }
        int cc = 4 * tp + j;
        int jj = cc / 3, kj = cc - jj * 3;
        int k9 = ki * 3 + kj;
        float v;
        if ((a & 1) == 0) {
            int ia = a >> 1;
            int px = i + ki + c_oxi[ia * 9 + k9];
            int py = jj + kj + c_oyi[ia * 9 + k9];
            v = (px >= 1 && px <= Hh && py >= 1 && py <= Ww)
                ? xp[(px - 1) * Ww + (py - 1)] : 0.f;
        } else {
            float sx = (float)(ki - 1) + c_ox[a * 9 + k9];
            float sy = (float)(kj - 1) + c_oy[a * 9 + k9];
            float px = (float)(i + 1) + sx;
            float py = (float)(jj + 1) + sy;
            float fx = floorf(px), fy = floorf(py);
            const float HI = 49.f;
            float ltx = fminf(fmaxf(fx,       0.f), HI);
            float lty = fminf(fmaxf(fy,       0.f), HI);
            float rbx = fminf(fmaxf(fx + 1.f, 0.f), HI);
            float rby = fminf(fmaxf(fy + 1.f, 0.f), HI);
            float pxc = fminf(fmaxf(px,       0.f), HI);
            float pyc = fminf(fmaxf(py,       0.f), HI);
            float g_lt = (1.f + (ltx - pxc)) * (1.f + (lty - pyc));
            float g_rb = (1.f - (rbx - pxc)) * (1.f - (rby - pyc));
            float g_lb = (1.f + (ltx - pxc)) * (1.f - (rby - pyc));
            float g_rt = (1.f - (rbx - pxc)) * (1.f + (lty - pyc));
            int ix0 = (int)ltx, iy0 = (int)lty, ix1 = (int)rbx, iy1 = (int)rby;
            auto gat = [&](int ix, int iy) -> float {
                ix -= 1; iy -= 1;
                if (ix < 0 || ix >= Hh || iy < 0 || iy >= Ww) return 0.f;
                return xp[ix * Ww + iy];
            };
            v = g_lt * gat(ix0, iy0) + g_rb * gat(ix1, iy1)
              + g_lb * gat(ix0, iy1) + g_rt * gat(ix1, iy0);
        }
        s[j] = v;
    }

    float v0[4] = { s[0] - s[2], s[1] + s[2], s[2] - s[1], s[1] - s[3] };
    float v1[4];
    if (tp == 35) { v1[0] = v1[1] = v1[2] = v1[3] = 0.f; }
    else {
        v1[0] = s[2] - s[4]; v1[1] = s[3] + s[4];
        v1[2] = s[4] - s[3]; v1[3] = s[3] - s[5];
    }

    size_t base = ((size_t)ab * C_ + c) * PLV + r * VW + 2 * tp;
#pragma unroll
    for (int cp = 0; cp < 4; cp++) {
        uint32_t pk = (uint32_t)__half_as_ushort(__float2half_rn(v0[cp]))
                    | ((uint32_t)__half_as_ushort(__float2half_rn(v1[cp])) << 16);
        *(uint32_t*)&g_v[(size_t)cp * CPSTR + base] = pk;
    }
}

// ---------------- 2) wino GEMM: 128x128 tile, CHUNK 64, double-buffered ----------------
__global__ void __launch_bounds__(256)
gemm_wino_kernel() {
    extern __shared__ char smem[];
    const uint32_t sb = smem_u32(smem);
    const int tid = threadIdx.x;
    const int cp  = blockIdx.z;
    const int ab  = blockIdx.y;
    const int coBase = (blockIdx.x & 1) * 128;
    const int nOff   = (blockIdx.x >> 1) * 128;
    const int lane = tid & 31, wid = tid >> 5;
    const int wm = wid & 3, wn = wid >> 2;

    const int aRow = tid >> 1, aPc = (tid & 1) * 4;   // 128 rows x 8 pieces (4/thread)
    const int bRow = tid >> 2, bPc = (tid & 3) * 4;   // 64 rows x 16 pieces (4/thread)

    const size_t vBase = (size_t)cp * CPSTR + (size_t)ab * C_ * PLV;

    auto issueChunk = [&](int ch, int st) {
        const uint32_t sg = sb + (uint32_t)st * STAGE;
        {   // A: 128 rows x 128B
            const char* src = (const char*)g_wU
                + ((size_t)(cp * C_ + coBase + aRow) * KW + (size_t)ch * CHUNK) * 2;
            uint32_t dst = sg + aRow * AROWB;
#pragma unroll
            for (int p = 0; p < 4; p++)
                cpasync16(dst + (aPc + p) * 16, src + (aPc + p) * 16);
        }
        {   // B: 64 k-rows x 256B
            int k  = ch * CHUNK + bRow;
            int ci = k / 3;
            int ki = k - ci * 3;
            const char* src = (const char*)g_v
                + (vBase + (size_t)ci * PLV + ki * VW + nOff) * 2;
            uint32_t dst = sg + OFF_B + bRow * BROWB;
#pragma unroll
            for (int p = 0; p < 4; p++)
                cpasync16(dst + (bPc + p) * 16, src + (bPc + p) * 16);
        }
    };

    float4 acc[2][8];
#pragma unroll
    for (int i = 0; i < 2; i++)
#pragma unroll
        for (int j = 0; j < 8; j++) acc[i][j] = make_float4(0.f, 0.f, 0.f, 0.f);

    const uint32_t aLd = (uint32_t)(wm * 32 + (lane & 15)) * AROWB + (uint32_t)(lane >> 4) * 16;
    const uint32_t bLd0 = (uint32_t)(lane & 15) * BROWB
                        + (uint32_t)(wn * 64 + (lane >> 4) * 8) * 2;

    auto computeStage = [&](int st) {
        const uint32_t sg = sb + (uint32_t)st * STAGE;
#pragma unroll
        for (int ks = 0; ks < 4; ks++) {
            uint32_t aH[2][4], bV[4][4];
#pragma unroll
            for (int mt = 0; mt < 2; mt++)
                ldmx4(aH[mt], sg + aLd + (uint32_t)(mt * 16) * AROWB + ks * 32);
#pragma unroll
            for (int bt = 0; bt < 4; bt++)
                ldmx4t(bV[bt], sg + OFF_B + bLd0 + (uint32_t)(ks * 16) * BROWB + (uint32_t)(bt * 16) * 2);
#pragma unroll
            for (int mt = 0; mt < 2; mt++)
#pragma unroll
                for (int nt = 0; nt < 8; nt++) {
                    uint32_t b0 = bV[nt >> 1][(nt & 1) * 2], b1 = bV[nt >> 1][(nt & 1) * 2 + 1];
                    mma_fp16(acc[mt][nt], aH[mt], b0, b1);
                }
        }
    };

    // prologue: stage 0
    issueChunk(0, 0);
    cp_commit();

    for (int ch = 0; ch < NCH; ch++) {
        cp_wait0();                 // chunk ch loaded
        __syncthreads();            // all threads done with compute(ch-1) + data visible
        if (ch + 1 < NCH) { issueChunk(ch + 1, (ch + 1) & 1); cp_commit(); }
        computeStage(ch & 1);
    }

    const int r0 = lane >> 2;
    const int cq = (lane & 3) * 2;
    __half* Mp = g_M + (size_t)(cp * NA * B_ + ab) * ((size_t)C_ * NPAD);
#pragma unroll
    for (int mt = 0; mt < 2; mt++) {
        int co0 = coBase + wm * 32 + mt * 16 + r0;
        int co1 = co0 + 8;
#pragma unroll
        for (int nt = 0; nt < 8; nt++) {
            int n0 = nOff + wn * 64 + nt * 8 + cq;
            float4 d = acc[mt][nt];
            *(__half2*)&Mp[(size_t)co0 * NPAD + n0] = __floats2half2_rn(d.x, d.y);
            *(__half2*)&Mp[(size_t)co1 * NPAD + n0] = __floats2half2_rn(d.z, d.w);
        }
    }
}

// ---------------- 3) GAP from M (a=1..4), uint4 loads ----------------
__global__ void __launch_bounds__(256)
gap_kernel(const float* __restrict__ gma, const float* __restrict__ bta,
           const float* __restrict__ mu,  const float* __restrict__ var) {
    const int blk = blockIdx.x;          // bb*C + co
    const int co = blk & 255;
    const int bb = blk >> 8;

    float sc[4], sh[4];
#pragma unroll
    for (int br = 0; br < 4; br++) {
        float vv = var[br * C_ + co];
        sc[br] = gma[br * C_ + co] * rsqrtf(vv + 1e-5f);
        sh[br] = bta[br * C_ + co] - mu[br * C_ + co] * sc[br];
    }

    const size_t MCP = (size_t)NA * B_ * C_ * NPAD;
    const __half* mp[4][4];
#pragma unroll
    for (int br = 0; br < 4; br++)
#pragma unroll
        for (int cpp = 0; cpp < 4; cpp++)
            mp[br][cpp] = g_M + (size_t)cpp * MCP
                        + (((size_t)((br + 1) * 2 + bb) * C_ + co) * NPAD);

    float s = 0.f;
    for (int i = threadIdx.x; i < NITER8; i += 256) {
        int u = i / 9, oc = i - u * 9;
        int np = u * VW + 8 * oc;
        int jmax = (oc == 8) ? 7 : 8;
#pragma unroll
        for (int br = 0; br < 4; br++) {
            float M0[8], M1[8], M2[8], M3[8];
            up8(*(const uint4*)&mp[br][0][np], M0);
            up8(*(const uint4*)&mp[br][1][np], M1);
            up8(*(const uint4*)&mp[br][2][np], M2);
            up8(*(const uint4*)&mp[br][3][np], M3);
#pragma unroll
            for (int j = 0; j < 8; j++) {
                if (j >= jmax) continue;
                float o0 = M0[j] + M1[j] + M2[j];
                float o1 = M1[j] - M2[j] - M3[j];
                s += fmaxf(fmaf(o0, sc[br], sh[br]), 0.f)
                   + fmaxf(fmaf(o1, sc[br], sh[br]), 0.f);
            }
        }
    }

    __shared__ float sm[256];
    sm[threadIdx.x] = s;
    __syncthreads();
    for (int st = 128; st > 0; st >>= 1) {
        if (threadIdx.x < st) sm[threadIdx.x] += sm[threadIdx.x + st];
        __syncthreads();
    }
    if (threadIdx.x == 0) g_fsum[bb * C_ + co] = sm[0];
}

// ---------------- 4) attention ----------------
__global__ void __launch_bounds__(1024)
att_kernel(const float* __restrict__ fc1w, const float* __restrict__ fc1b,
           const float* __restrict__ fc2w, const float* __restrict__ fc2b) {
    extern __shared__ float sm[];
    float* sW1  = sm;
    float* sW2  = sm + 8192;
    float* sFs  = sm + 8192 + 32768;
    float* sZ   = sFs + 512;
    float* sAtt = sZ + 64;
    int t = threadIdx.x;

#pragma unroll
    for (int i = 0; i < 2; i++)
        ((float4*)sW1)[t + i * 1024] = ((const float4*)fc1w)[t + i * 1024];
#pragma unroll
    for (int i = 0; i < 8; i++) {
        int v4 = t + i * 1024;
        float4 w4 = ((const float4*)fc2w)[v4];
        int mc = v4 >> 3;
        int d0 = (v4 & 7) * 4;
        sW2[(d0 + 0) * 1024 + mc] = w4.x;
        sW2[(d0 + 1) * 1024 + mc] = w4.y;
        sW2[(d0 + 2) * 1024 + mc] = w4.z;
        sW2[(d0 + 3) * 1024 + mc] = w4.w;
    }
    if (t < B_ * C_) sFs[t] = g_fsum[t] * (1.f / (float)NPB);
    __syncthreads();

    {
        int pair = t >> 4;
        int b = pair >> 5, d = pair & 31;
        int sl = t & 15;
        float s = 0.f;
#pragma unroll
        for (int c = sl; c < C_; c += 16) s += sFs[b * C_ + c] * sW1[d * C_ + c];
        s += __shfl_down_sync(0xffffffffu, s, 8, 16);
        s += __shfl_down_sync(0xffffffffu, s, 4, 16);
        s += __shfl_down_sync(0xffffffffu, s, 2, 16);
        s += __shfl_down_sync(0xffffffffu, s, 1, 16);
        if (sl == 0) sZ[b * 32 + d] = s + fc1b[d];
    }
    __syncthreads();

#pragma unroll
    for (int i = 0; i < 2; i++) {
        int o = t + i * 1024;
        int b = o >> 10;
        int mc = o & 1023;
        float s = fc2b[mc];
#pragma unroll
        for (int d = 0; d < 32; d++) s += sZ[b * 32 + d] * sW2[d * 1024 + mc];
        sAtt[b * 1024 + mc] = s;
    }
    __syncthreads();

    if (t < B_ * C_) {
        int b = t >> 8, c = t & 255;
        float a0 = sAtt[b * 1024 + 0 * C_ + c];
        float a1 = sAtt[b * 1024 + 1 * C_ + c];
        float a2 = sAtt[b * 1024 + 2 * C_ + c];
        float a3 = sAtt[b * 1024 + 3 * C_ + c];
        float mx = fmaxf(fmaxf(a0, a1), fmaxf(a2, a3));
        float e0 = expf(a0 - mx), e1 = expf(a1 - mx), e2 = expf(a2 - mx), e3 = expf(a3 - mx);
        float inv = 1.f / (e0 + e1 + e2 + e3);
        g_att[(b * 4 + 0) * C_ + c] = e0 * inv;
        g_att[(b * 4 + 1) * C_ + c] = e1 * inv;
        g_att[(b * 4 + 2) * C_ + c] = e2 * inv;
        g_att[(b * 4 + 3) * C_ + c] = e3 * inv;
    }
}

// ---------------- 5) final: A^T + BN/ReLU + blend from M, uint4 loads ----------------
__global__ void __launch_bounds__(256)
final_kernel(const float* __restrict__ gma, const float* __restrict__ bta,
             const float* __restrict__ mu,  const float* __restrict__ var,
             float* __restrict__ out) {
    const int blk = blockIdx.x;          // bb*C + co
    const int co = blk & 255;
    const int bb = blk >> 8;

    float sc[4], sh[4], aw[4];
#pragma unroll
    for (int br = 0; br < 4; br++) {
        float vv = var[br * C_ + co];
        sc[br] = gma[br * C_ + co] * rsqrtf(vv + 1e-5f);
        sh[br] = bta[br * C_ + co] - mu[br * C_ + co] * sc[br];
        aw[br] = g_att[(bb * 4 + br) * C_ + co];
    }

    const size_t MCP = (size_t)NA * B_ * C_ * NPAD;
    const __half* mp[5][4];
#pragma unroll
    for (int a = 0; a < 5; a++)
#pragma unroll
        for (int cpp = 0; cpp < 4; cpp++)
            mp[a][cpp] = g_M + (size_t)cpp * MCP
                       + (((size_t)(a * 2 + bb) * C_ + co) * NPAD);

    float* op = out + (size_t)(bb * C_ + co) * NPB;

    for (int i = threadIdx.x; i < NITER8; i += 256) {
        int u = i / 9, oc = i - u * 9;
        int np = u * VW + 8 * oc;
        int jmax = (oc == 8) ? 7 : 8;

        float acc0[8], acc1[8];
        {   // a = 0: identity branch
            float M0[8], M1[8], M2[8], M3[8];
            up8(*(const uint4*)&mp[0][0][np], M0);
            up8(*(const uint4*)&mp[0][1][np], M1);
            up8(*(const uint4*)&mp[0][2][np], M2);
            up8(*(const uint4*)&mp[0][3][np], M3);
#pragma unroll
            for (int j = 0; j < 8; j++) {
                acc0[j] = M0[j] + M1[j] + M2[j];
                acc1[j] = M1[j] - M2[j] - M3[j];
            }
        }
#pragma unroll
        for (int br = 0; br < 4; br++) {
            float M0[8], M1[8], M2[8], M3[8];
            up8(*(const uint4*)&mp[br + 1][0][np], M0);
            up8(*(const uint4*)&mp[br + 1][1][np], M1);
            up8(*(const uint4*)&mp[br + 1][2][np], M2);
            up8(*(const uint4*)&mp[br + 1][3][np], M3);
#pragma unroll
            for (int j = 0; j < 8; j++) {
                float o0 = M0[j] + M1[j] + M2[j];
                float o1 = M1[j] - M2[j] - M3[j];
                float f0 = fmaxf(fmaf(o0, sc[br], sh[br]), 0.f);
                float f1 = fmaxf(fmaf(o1, sc[br], sh[br]), 0.f);
                acc0[j] = fmaf(f0, aw[br], acc0[j]);
                acc1[j] = fmaf(f1, aw[br], acc1[j]);
            }
        }
        int p = u * WO + 16 * oc;
#pragma unroll
        for (int j = 0; j < 8; j++) {
            if (j >= jmax) continue;
            *(float2*)&op[p + 2 * j] = make_float2(acc0[j], acc1[j]);
        }
    }
}

// ---------------- launch ----------------
extern "C" void kernel_launch(void* const* d_in, const int* in_sizes, int n_in,
                              void* d_out, int out_size) {
    const float* x    = (const float*)d_in[0];
    const float* w    = (const float*)d_in[1];
    const float* gma  = (const float*)d_in[2];
    const float* bta  = (const float*)d_in[3];
    const float* mu   = (const float*)d_in[4];
    const float* var  = (const float*)d_in[5];
    const float* fc1w = (const float*)d_in[6];
    const float* fc1b = (const float*)d_in[7];
    const float* fc2w = (const float*)d_in[8];
    const float* fc2b = (const float*)d_in[9];
    float* out = (float*)d_out;

    cudaFuncSetAttribute(gemm_wino_kernel,
                         cudaFuncAttributeMaxDynamicSharedMemorySize, SMEM_TOTAL);
    cudaFuncSetAttribute(att_kernel,
                         cudaFuncAttributeMaxDynamicSharedMemorySize, ATT_SMEM);

    prep_kernel<<<(C_ * KW + 255) / 256, 256>>>(w);

    dim3 sgrid(81, C_ / 4, NA * B_);
    sampleV_kernel<<<sgrid, 256>>>(x);

    dim3 ggrid(2 * NT, NA * B_, 4);
    gemm_wino_kernel<<<ggrid, 256, SMEM_TOTAL>>>();

    gap_kernel<<<B_ * C_, 256>>>(gma, bta, mu, var);
    att_kernel<<<1, 1024, ATT_SMEM>>>(fc1w, fc1b, fc2w, fc2b);
    final_kernel<<<B_ * C_, 256>>>(gma, bta, mu, var, out);
}

// round 17
// speedup vs baseline: 1.1864x; 1.1864x over previous
#include <cuda_runtime.h>
#include <cuda_fp16.h>
#include <cstdint>

// ---------------- problem constants ----------------
constexpr int B_   = 2;
constexpr int C_   = 256;
constexpr int Hh   = 48;
constexpr int Ww   = 48;
constexpr int H3   = 144;
constexpr int HO   = 142, WO = 142;
constexpr int NPB  = HO * WO;        // 20164
constexpr int NA   = 5;

// Winograd F(2,3) along v: 4 components, K = C*3
constexpr int KW   = C_ * 3;         // 768
constexpr int VW   = 72;             // V row width (71 valid tiles + 1 pad)
constexpr int PLV  = H3 * VW;        // 10368
constexpr size_t CPSTR = (size_t)NA * B_ * C_ * PLV;
constexpr int PADE = 8192;

// GEMM tiling (r12-proven): 128co x 128n, 256 threads, CHUNK 32, 4 stages
constexpr int NPAD  = 10240;         // 80 tiles * 128
constexpr int NT    = 80;
constexpr int CHUNK = 32;
constexpr int NCH   = KW / CHUNK;    // 24
constexpr int NS    = 4;
constexpr int AROWB = 80;
constexpr int BROWB = 272;
constexpr int OFF_B = 128 * AROWB;                 // 10240
constexpr int STAGE = OFF_B + 32 * BROWB;          // 18944
constexpr int SMEM_TOTAL = NS * STAGE;             // 75776

constexpr int ATT_SMEM = (8192 + 32768 + 512 + 64 + 2048) * 4;  // 174336

// vector-iteration space over M planes: 142 rows x 9 octs (8 tiles each)
constexpr int NITER8 = HO * 9;       // 1278

// ---------------- static scratch ----------------
__device__ __align__(16) unsigned short g_v[4 * CPSTR + PADE];
__device__ __align__(16) unsigned short g_wU[4 * C_ * KW];
__device__ __align__(16) __half g_M[(size_t)4 * NA * B_ * C_ * NPAD];
__device__ float g_fsum[B_ * C_];
__device__ float g_att[B_ * 4 * C_];

// ---------------- angle offset tables ----------------
#define S2  1.4142135623730951
#define S2H 0.7071067811865476
__constant__ float c_ox[45] = {
    0.f,0.f,0.f,0.f,0.f,0.f,0.f,0.f,0.f,
    (float)(1.0-S2), (float)(1.0-S2H), 1.f, (float)(-S2H), 0.f, (float)(S2H),
    -1.f, (float)(S2H-1.0), (float)(S2-1.0),
    0.f,1.f,2.f,-1.f,0.f,1.f,-2.f,-1.f,0.f,
    1.f, (float)(1.0+S2H), (float)(1.0+S2), (float)(-S2H), 0.f, (float)(S2H),
    (float)(-1.0-S2), (float)(-1.0-S2H), -1.f,
    2.f,2.f,2.f,0.f,0.f,0.f,-2.f,-2.f,-2.f
};
__constant__ float c_oy[45] = {
    0.f,0.f,0.f,0.f,0.f,0.f,0.f,0.f,0.f,
    1.f, (float)(S2H), (float)(S2-1.0), (float)(1.0-S2H), 0.f, (float)(S2H-1.0),
    (float)(1.0-S2), (float)(-S2H), -1.f,
    2.f,1.f,0.f,1.f,0.f,-1.f,0.f,-1.f,-2.f,
    (float)(1.0+S2), (float)(S2H), -1.f, (float)(1.0+S2H), 0.f, (float)(-1.0-S2H),
    1.f, (float)(-S2H), (float)(1.0+S2),
    2.f,0.f,-2.f,2.f,0.f,-2.f,2.f,0.f,-2.f
};
__constant__ int c_oxi[27] = {
    0,0,0,0,0,0,0,0,0,
    0,1,2,-1,0,1,-2,-1,0,
    2,2,2,0,0,0,-2,-2,-2
};
__constant__ int c_oyi[27] = {
    0,0,0,0,0,0,0,0,0,
    2,1,0,1,0,-1,0,-1,-2,
    2,0,-2,2,0,-2,2,0,-2
};

// ---------------- helpers ----------------
__device__ __forceinline__ uint32_t smem_u32(const void* p) {
    uint32_t a;
    asm("{ .reg .u64 t; cvta.to.shared.u64 t, %1; cvt.u32.u64 %0, t; }" : "=r"(a) : "l"(p));
    return a;
}
__device__ __forceinline__ void cpasync16(uint32_t dst, const void* src) {
    asm volatile("cp.async.cg.shared.global [%0], [%1], 16;" :: "r"(dst), "l"(src));
}
__device__ __forceinline__ void cp_commit() {
    asm volatile("cp.async.commit_group;" ::: "memory");
}
__device__ __forceinline__ void cp_wait2() {
    asm volatile("cp.async.wait_group %0;" :: "n"(2) : "memory");
}
__device__ __forceinline__ void ldmx4(uint32_t* r, uint32_t addr) {
    asm volatile("ldmatrix.sync.aligned.m8n8.x4.shared.b16 {%0,%1,%2,%3}, [%4];"
                 : "=r"(r[0]), "=r"(r[1]), "=r"(r[2]), "=r"(r[3]) : "r"(addr));
}
__device__ __forceinline__ void ldmx4t(uint32_t* r, uint32_t addr) {
    asm volatile("ldmatrix.sync.aligned.m8n8.x4.trans.shared.b16 {%0,%1,%2,%3}, [%4];"
                 : "=r"(r[0]), "=r"(r[1]), "=r"(r[2]), "=r"(r[3]) : "r"(addr));
}
__device__ __forceinline__ void mma_fp16(float4& d, const uint32_t a[4], uint32_t b0, uint32_t b1) {
    asm volatile("mma.sync.aligned.m16n8k16.row.col.f32.f16.f16.f32 "
                 "{%0,%1,%2,%3}, {%4,%5,%6,%7}, {%8,%9}, {%0,%1,%2,%3};"
                 : "+f"(d.x), "+f"(d.y), "+f"(d.z), "+f"(d.w)
                 : "r"(a[0]), "r"(a[1]), "r"(a[2]), "r"(a[3]), "r"(b0), "r"(b1));
}
__device__ __forceinline__ void up8(uint4 v, float* f) {
    float2 a = __half22float2(*(__half2*)&v.x);
    float2 b = __half22float2(*(__half2*)&v.y);
    float2 c = __half22float2(*(__half2*)&v.z);
    float2 d = __half22float2(*(__half2*)&v.w);
    f[0] = a.x; f[1] = a.y; f[2] = b.x; f[3] = b.y;
    f[4] = c.x; f[5] = c.y; f[6] = d.x; f[7] = d.y;
}

// ---------------- 0) prep: weight winograd transform ----------------
__global__ void prep_kernel(const float* __restrict__ w) {
    int i = blockIdx.x * blockDim.x + threadIdx.x;
    if (i >= C_ * KW) return;
    int co = i / KW;
    int k  = i - co * KW;          // ci*3 + ki
    int ci = k / 3, ki = k - ci * 3;
    const float* gp = w + (((size_t)co * C_ + ci) * 3 + ki) * 3;
    float g0 = gp[0], g1 = gp[1], g2 = gp[2];
    g_wU[(0 * C_ + co) * KW + k] = __half_as_ushort(__float2half_rn(g0));
    g_wU[(1 * C_ + co) * KW + k] = __half_as_ushort(__float2half_rn(0.5f * (g0 + g1 + g2)));
    g_wU[(2 * C_ + co) * KW + k] = __half_as_ushort(__float2half_rn(0.5f * (g0 - g1 + g2)));
    g_wU[(3 * C_ + co) * KW + k] = __half_as_ushort(__float2half_rn(g2));
}

// ---------------- 1) fused bilinear resample + V transform ----------------
// grid: (81, 64, NA*B_), block 256 = 4 channels x 64 ip-slots
__global__ void sampleV_kernel(const float* __restrict__ x) {
    int ip = blockIdx.x * 64 + (threadIdx.x & 63);  // [0, 5184)
    int c  = blockIdx.y * 4 + (threadIdx.x >> 6);
    int ab = blockIdx.z;
    int a  = ab >> 1, bb = ab & 1;

    int r  = ip / 36;
    int tp = ip - r * 36;

    int i = r / 3, ki = r - i * 3;
    const float* xp = x + (bb * C_ + c) * (Hh * Ww);

    float s[6];
    int jmax = (tp == 35) ? 4 : 6;
    for (int j = 0; j < 6; j++) {
        if (j >= jmax) { s[j] = 0.f; continue; }
        int cc = 4 * tp + j;
        int jj = cc / 3, kj = cc - jj * 3;
        int k9 = ki * 3 + kj;
        float v;
        if ((a & 1) == 0) {
            int ia = a >> 1;
            int px = i + ki + c_oxi[ia * 9 + k9];
            int py = jj + kj + c_oyi[ia * 9 + k9];
            v = (px >= 1 && px <= Hh && py >= 1 && py <= Ww)
                ? xp[(px - 1) * Ww + (py - 1)] : 0.f;
        } else {
            float sx = (float)(ki - 1) + c_ox[a * 9 + k9];
            float sy = (float)(kj - 1) + c_oy[a * 9 + k9];
            float px = (float)(i + 1) + sx;
            float py = (float)(jj + 1) + sy;
            float fx = floorf(px), fy = floorf(py);
            const float HI = 49.f;
            float ltx = fminf(fmaxf(fx,       0.f), HI);
            float lty = fminf(fmaxf(fy,       0.f), HI);
            float rbx = fminf(fmaxf(fx + 1.f, 0.f), HI);
            float rby = fminf(fmaxf(fy + 1.f, 0.f), HI);
            float pxc = fminf(fmaxf(px,       0.f), HI);
            float pyc = fminf(fmaxf(py,       0.f), HI);
            float g_lt = (1.f + (ltx - pxc)) * (1.f + (lty - pyc));
            float g_rb = (1.f - (rbx - pxc)) * (1.f - (rby - pyc));
            float g_lb = (1.f + (ltx - pxc)) * (1.f - (rby - pyc));
            float g_rt = (1.f - (rbx - pxc)) * (1.f + (lty - pyc));
            int ix0 = (int)ltx, iy0 = (int)lty, ix1 = (int)rbx, iy1 = (int)rby;
            auto gat = [&](int ix, int iy) -> float {
                ix -= 1; iy -= 1;
                if (ix < 0 || ix >= Hh || iy < 0 || iy >= Ww) return 0.f;
                return xp[ix * Ww + iy];
            };
            v = g_lt * gat(ix0, iy0) + g_rb * gat(ix1, iy1)
              + g_lb * gat(ix0, iy1) + g_rt * gat(ix1, iy0);
        }
        s[j] = v;
    }

    float v0[4] = { s[0] - s[2], s[1] + s[2], s[2] - s[1], s[1] - s[3] };
    float v1[4];
    if (tp == 35) { v1[0] = v1[1] = v1[2] = v1[3] = 0.f; }
    else {
        v1[0] = s[2] - s[4]; v1[1] = s[3] + s[4];
        v1[2] = s[4] - s[3]; v1[3] = s[3] - s[5];
    }

    size_t base = ((size_t)ab * C_ + c) * PLV + r * VW + 2 * tp;
#pragma unroll
    for (int cp = 0; cp < 4; cp++) {
        uint32_t pk = (uint32_t)__half_as_ushort(__float2half_rn(v0[cp]))
                    | ((uint32_t)__half_as_ushort(__float2half_rn(v1[cp])) << 16);
        *(uint32_t*)&g_v[(size_t)cp * CPSTR + base] = pk;
    }
}

// ---------------- 2) wino GEMM: r12-proven 128x128 tile, 256 threads ----------------
__global__ void __launch_bounds__(256)
gemm_wino_kernel() {
    extern __shared__ char smem[];
    const uint32_t sb = smem_u32(smem);
    const int tid = threadIdx.x;
    const int cp  = blockIdx.z;
    const int ab  = blockIdx.y;
    const int coBase = (blockIdx.x & 1) * 128;
    const int nOff   = (blockIdx.x >> 1) * 128;
    const int lane = tid & 31, wid = tid >> 5;
    const int wm = wid & 3, wn = wid >> 2;

    const int aRow = tid >> 2, aPc = tid & 3;
    const int bRow = tid >> 4, bPc = tid & 15;

    const size_t vBase = (size_t)cp * CPSTR + (size_t)ab * C_ * PLV;

    auto issueChunk = [&](int ch, int st) {
        const uint32_t sg = sb + (uint32_t)st * STAGE;
#pragma unroll
        for (int t2 = 0; t2 < 2; t2++) {
            int row = aRow + t2 * 64;
            const char* src = (const char*)g_wU
                + ((size_t)(cp * C_ + coBase + row) * KW + (size_t)ch * CHUNK) * 2 + aPc * 16;
            cpasync16(sg + row * AROWB + aPc * 16, src);
        }
#pragma unroll
        for (int t2 = 0; t2 < 2; t2++) {
            int row = bRow + t2 * 16;
            int k  = ch * CHUNK + row;
            int ci = k / 3;
            int ki = k - ci * 3;
            const char* src = (const char*)g_v
                + (vBase + (size_t)ci * PLV + ki * VW + nOff) * 2 + bPc * 16;
            cpasync16(sg + OFF_B + row * BROWB + bPc * 16, src);
        }
    };

    float4 acc[2][8];
#pragma unroll
    for (int i = 0; i < 2; i++)
#pragma unroll
        for (int j = 0; j < 8; j++) acc[i][j] = make_float4(0.f, 0.f, 0.f, 0.f);

    const uint32_t aLd = (uint32_t)(wm * 32 + (lane & 15)) * AROWB + (uint32_t)(lane >> 4) * 16;
    const uint32_t bLd0 = (uint32_t)(lane & 15) * BROWB
                        + (uint32_t)(wn * 64 + (lane >> 4) * 8) * 2;

    auto computeStage = [&](int st) {
        const uint32_t sg = sb + (uint32_t)st * STAGE;
#pragma unroll
        for (int ks = 0; ks < 2; ks++) {
            uint32_t aH[2][4], bV[4][4];
#pragma unroll
            for (int mt = 0; mt < 2; mt++)
                ldmx4(aH[mt], sg + aLd + (uint32_t)(mt * 16) * AROWB + ks * 32);
#pragma unroll
            for (int bt = 0; bt < 4; bt++)
                ldmx4t(bV[bt], sg + OFF_B + bLd0 + (uint32_t)(ks * 16) * BROWB + (uint32_t)(bt * 16) * 2);
#pragma unroll
            for (int mt = 0; mt < 2; mt++)
#pragma unroll
                for (int nt = 0; nt < 8; nt++) {
                    uint32_t b0 = bV[nt >> 1][(nt & 1) * 2], b1 = bV[nt >> 1][(nt & 1) * 2 + 1];
                    mma_fp16(acc[mt][nt], aH[mt], b0, b1);
                }
        }
    };

#pragma unroll
    for (int s = 0; s < NS - 1; s++) { issueChunk(s, s); cp_commit(); }

    for (int ch = 0; ch < NCH; ch++) {
        cp_wait2();
        __syncthreads();
        if (ch + NS - 1 < NCH) issueChunk(ch + NS - 1, (ch + NS - 1) & (NS - 1));
        cp_commit();
        computeStage(ch & (NS - 1));
    }

    const int r0 = lane >> 2;
    const int cq = (lane & 3) * 2;
    __half* Mp = g_M + (size_t)(cp * NA * B_ + ab) * ((size_t)C_ * NPAD);
#pragma unroll
    for (int mt = 0; mt < 2; mt++) {
        int co0 = coBase + wm * 32 + mt * 16 + r0;
        int co1 = co0 + 8;
#pragma unroll
        for (int nt = 0; nt < 8; nt++) {
            int n0 = nOff + wn * 64 + nt * 8 + cq;
            float4 d = acc[mt][nt];
            *(__half2*)&Mp[(size_t)co0 * NPAD + n0] = __floats2half2_rn(d.x, d.y);
            *(__half2*)&Mp[(size_t)co1 * NPAD + n0] = __floats2half2_rn(d.z, d.w);
        }
    }
}

// ---------------- 3) GAP from M (a=1..4), uint4 loads ----------------
__global__ void __launch_bounds__(256)
gap_kernel(const float* __restrict__ gma, const float* __restrict__ bta,
           const float* __restrict__ mu,  const float* __restrict__ var) {
    const int blk = blockIdx.x;          // bb*C + co
    const int co = blk & 255;
    const int bb = blk >> 8;

    float sc[4], sh[4];
#pragma unroll
    for (int br = 0; br < 4; br++) {
        float vv = var[br * C_ + co];
        sc[br] = gma[br * C_ + co] * rsqrtf(vv + 1e-5f);
        sh[br] = bta[br * C_ + co] - mu[br * C_ + co] * sc[br];
    }

    const size_t MCP = (size_t)NA * B_ * C_ * NPAD;
    const __half* mp[4][4];
#pragma unroll
    for (int br = 0; br < 4; br++)
#pragma unroll
        for (int cpp = 0; cpp < 4; cpp++)
            mp[br][cpp] = g_M + (size_t)cpp * MCP
                        + (((size_t)((br + 1) * 2 + bb) * C_ + co) * NPAD);

    float s = 0.f;
    for (int i = threadIdx.x; i < NITER8; i += 256) {
        int u = i / 9, oc = i - u * 9;
        int np = u * VW + 8 * oc;
        int jmax = (oc == 8) ? 7 : 8;
#pragma unroll
        for (int br = 0; br < 4; br++) {
            float M0[8], M1[8], M2[8], M3[8];
            up8(*(const uint4*)&mp[br][0][np], M0);
            up8(*(const uint4*)&mp[br][1][np], M1);
            up8(*(const uint4*)&mp[br][2][np], M2);
            up8(*(const uint4*)&mp[br][3][np], M3);
#pragma unroll
            for (int j = 0; j < 8; j++) {
                if (j >= jmax) continue;
                float o0 = M0[j] + M1[j] + M2[j];
                float o1 = M1[j] - M2[j] - M3[j];
                s += fmaxf(fmaf(o0, sc[br], sh[br]), 0.f)
                   + fmaxf(fmaf(o1, sc[br], sh[br]), 0.f);
            }
        }
    }

    __shared__ float sm[256];
    sm[threadIdx.x] = s;
    __syncthreads();
    for (int st = 128; st > 0; st >>= 1) {
        if (threadIdx.x < st) sm[threadIdx.x] += sm[threadIdx.x + st];
        __syncthreads();
    }
    if (threadIdx.x == 0) g_fsum[bb * C_ + co] = sm[0];
}

// ---------------- 4) attention ----------------
__global__ void __launch_bounds__(1024)
att_kernel(const float* __restrict__ fc1w, const float* __restrict__ fc1b,
           const float* __restrict__ fc2w, const float* __restrict__ fc2b) {
    extern __shared__ float sm[];
    float* sW1  = sm;
    float* sW2  = sm + 8192;
    float* sFs  = sm + 8192 + 32768;
    float* sZ   = sFs + 512;
    float* sAtt = sZ + 64;
    int t = threadIdx.x;

#pragma unroll
    for (int i = 0; i < 2; i++)
        ((float4*)sW1)[t + i * 1024] = ((const float4*)fc1w)[t + i * 1024];
#pragma unroll
    for (int i = 0; i < 8; i++) {
        int v4 = t + i * 1024;
        float4 w4 = ((const float4*)fc2w)[v4];
        int mc = v4 >> 3;
        int d0 = (v4 & 7) * 4;
        sW2[(d0 + 0) * 1024 + mc] = w4.x;
        sW2[(d0 + 1) * 1024 + mc] = w4.y;
        sW2[(d0 + 2) * 1024 + mc] = w4.z;
        sW2[(d0 + 3) * 1024 + mc] = w4.w;
    }
    if (t < B_ * C_) sFs[t] = g_fsum[t] * (1.f / (float)NPB);
    __syncthreads();

    {
        int pair = t >> 4;
        int b = pair >> 5, d = pair & 31;
        int sl = t & 15;
        float s = 0.f;
#pragma unroll
        for (int c = sl; c < C_; c += 16) s += sFs[b * C_ + c] * sW1[d * C_ + c];
        s += __shfl_down_sync(0xffffffffu, s, 8, 16);
        s += __shfl_down_sync(0xffffffffu, s, 4, 16);
        s += __shfl_down_sync(0xffffffffu, s, 2, 16);
        s += __shfl_down_sync(0xffffffffu, s, 1, 16);
        if (sl == 0) sZ[b * 32 + d] = s + fc1b[d];
    }
    __syncthreads();

#pragma unroll
    for (int i = 0; i < 2; i++) {
        int o = t + i * 1024;
        int b = o >> 10;
        int mc = o & 1023;
        float s = fc2b[mc];
#pragma unroll
        for (int d = 0; d < 32; d++) s += sZ[b * 32 + d] * sW2[d * 1024 + mc];
        sAtt[b * 1024 + mc] = s;
    }
    __syncthreads();

    if (t < B_ * C_) {
        int b = t >> 8, c = t & 255;
        float a0 = sAtt[b * 1024 + 0 * C_ + c];
        float a1 = sAtt[b * 1024 + 1 * C_ + c];
        float a2 = sAtt[b * 1024 + 2 * C_ + c];
        float a3 = sAtt[b * 1024 + 3 * C_ + c];
        float mx = fmaxf(fmaxf(a0, a1), fmaxf(a2, a3));
        float e0 = expf(a0 - mx), e1 = expf(a1 - mx), e2 = expf(a2 - mx), e3 = expf(a3 - mx);
        float inv = 1.f / (e0 + e1 + e2 + e3);
        g_att[(b * 4 + 0) * C_ + c] = e0 * inv;
        g_att[(b * 4 + 1) * C_ + c] = e1 * inv;
        g_att[(b * 4 + 2) * C_ + c] = e2 * inv;
        g_att[(b * 4 + 3) * C_ + c] = e3 * inv;
    }
}

// ---------------- 5) final: A^T + BN/ReLU + blend from M, uint4 loads ----------------
__global__ void __launch_bounds__(256)
final_kernel(const float* __restrict__ gma, const float* __restrict__ bta,
             const float* __restrict__ mu,  const float* __restrict__ var,
             float* __restrict__ out) {
    const int blk = blockIdx.x;          // bb*C + co
    const int co = blk & 255;
    const int bb = blk >> 8;

    float sc[4], sh[4], aw[4];
#pragma unroll
    for (int br = 0; br < 4; br++) {
        float vv = var[br * C_ + co];
        sc[br] = gma[br * C_ + co] * rsqrtf(vv + 1e-5f);
        sh[br] = bta[br * C_ + co] - mu[br * C_ + co] * sc[br];
        aw[br] = g_att[(bb * 4 + br) * C_ + co];
    }

    const size_t MCP = (size_t)NA * B_ * C_ * NPAD;
    const __half* mp[5][4];
#pragma unroll
    for (int a = 0; a < 5; a++)
#pragma unroll
        for (int cpp = 0; cpp < 4; cpp++)
            mp[a][cpp] = g_M + (size_t)cpp * MCP
                       + (((size_t)(a * 2 + bb) * C_ + co) * NPAD);

    float* op = out + (size_t)(bb * C_ + co) * NPB;

    for (int i = threadIdx.x; i < NITER8; i += 256) {
        int u = i / 9, oc = i - u * 9;
        int np = u * VW + 8 * oc;
        int jmax = (oc == 8) ? 7 : 8;

        float acc0[8], acc1[8];
        {   // a = 0: identity branch
            float M0[8], M1[8], M2[8], M3[8];
            up8(*(const uint4*)&mp[0][0][np], M0);
            up8(*(const uint4*)&mp[0][1][np], M1);
            up8(*(const uint4*)&mp[0][2][np], M2);
            up8(*(const uint4*)&mp[0][3][np], M3);
#pragma unroll
            for (int j = 0; j < 8; j++) {
                acc0[j] = M0[j] + M1[j] + M2[j];
                acc1[j] = M1[j] - M2[j] - M3[j];
            }
        }
#pragma unroll
        for (int br = 0; br < 4; br++) {
            float M0[8], M1[8], M2[8], M3[8];
            up8(*(const uint4*)&mp[br + 1][0][np], M0);
            up8(*(const uint4*)&mp[br + 1][1][np], M1);
            up8(*(const uint4*)&mp[br + 1][2][np], M2);
            up8(*(const uint4*)&mp[br + 1][3][np], M3);
#pragma unroll
            for (int j = 0; j < 8; j++) {
                float o0 = M0[j] + M1[j] + M2[j];
                float o1 = M1[j] - M2[j] - M3[j];
                float f0 = fmaxf(fmaf(o0, sc[br], sh[br]), 0.f);
                float f1 = fmaxf(fmaf(o1, sc[br], sh[br]), 0.f);
                acc0[j] = fmaf(f0, aw[br], acc0[j]);
                acc1[j] = fmaf(f1, aw[br], acc1[j]);
            }
        }
        int p = u * WO + 16 * oc;
#pragma unroll
        for (int j = 0; j < 8; j++) {
            if (j >= jmax) continue;
            *(float2*)&op[p + 2 * j] = make_float2(acc0[j], acc1[j]);
        }
    }
}

// ---------------- launch ----------------
extern "C" void kernel_launch(void* const* d_in, const int* in_sizes, int n_in,
                              void* d_out, int out_size) {
    const float* x    = (const float*)d_in[0];
    const float* w    = (const float*)d_in[1];
    const float* gma  = (const float*)d_in[2];
    const float* bta  = (const float*)d_in[3];
    const float* mu   = (const float*)d_in[4];
    const float* var  = (const float*)d_in[5];
    const float* fc1w = (const float*)d_in[6];
    const float* fc1b = (const float*)d_in[7];
    const float* fc2w = (const float*)d_in[8];
    const float* fc2b = (const float*)d_in[9];
    float* out = (float*)d_out;

    cudaFuncSetAttribute(gemm_wino_kernel,
                         cudaFuncAttributeMaxDynamicSharedMemorySize, SMEM_TOTAL);
    cudaFuncSetAttribute(att_kernel,
                         cudaFuncAttributeMaxDynamicSharedMemorySize, ATT_SMEM);

    prep_kernel<<<(C_ * KW + 255) / 256, 256>>>(w);

    dim3 sgrid(81, C_ / 4, NA * B_);
    sampleV_kernel<<<sgrid, 256>>>(x);

    dim3 ggrid(2 * NT, NA * B_, 4);
    gemm_wino_kernel<<<ggrid, 256, SMEM_TOTAL>>>();

    gap_kernel<<<B_ * C_, 256>>>(gma, bta, mu, var);
    att_kernel<<<1, 1024, ATT_SMEM>>>(fc1w, fc1b, fc2w, fc2b);
    final_kernel<<<B_ * C_, 256>>>(gma, bta, mu, var, out);
}